// round 1
// baseline (speedup 1.0000x reference)
#include <cuda_runtime.h>

typedef unsigned long long ULL;

__device__ __forceinline__ ULL fma2(ULL a, ULL b, ULL c) {
    ULL d;
    asm("fma.rn.f32x2 %0, %1, %2, %3;" : "=l"(d) : "l"(a), "l"(b), "l"(c));
    return d;
}
__device__ __forceinline__ ULL dup2(float x) {
    ULL d;
    asm("mov.b64 %0, {%1, %1};" : "=l"(d) : "f"(x));
    return d;
}
__device__ __forceinline__ float2 unpk(ULL v) {
    float2 r;
    asm("mov.b64 {%0, %1}, %2;" : "=f"(r.x), "=f"(r.y) : "l"(v));
    return r;
}

#define N_TOT 8192
#define P_TOT 512
#define TN 8          // n's per attention block

// Scratch (static device globals — no allocation)
__device__ float2 g_ca2T[16 * 512];    // [k][p] : (ca[p][2k], ca[p][2k+1])
__device__ float2 g_qa2[N_TOT * 16];   // [n][k] : (qa[n][2k], qa[n][2k+1])
__device__ float  g_c[N_TOT * 16];     // pooled-projection output c (N,16)

// ---------------------------------------------------------------------------
// Precompute ca = coeff_x @ Wa1[2:4]  (transposed/packed layout)
__global__ void pre_ca(const float* __restrict__ cx, const float* __restrict__ Wa1) {
    int idx = blockIdx.x * blockDim.x + threadIdx.x;   // 8192 = 512p * 16k
    int p = idx & 511, k = idx >> 9;
    float x0 = cx[p * 2 + 0], x1 = cx[p * 2 + 1];
    float c0 = x0 * Wa1[64 + 2 * k]     + x1 * Wa1[96 + 2 * k];
    float c1 = x0 * Wa1[64 + 2 * k + 1] + x1 * Wa1[96 + 2 * k + 1];
    g_ca2T[k * 512 + p] = make_float2(c0, c1);
}

// Precompute qa = r[:, :2] @ Wa1[0:2]
__global__ void pre_qa(const float* __restrict__ r, const float* __restrict__ Wa1) {
    int idx = blockIdx.x * blockDim.x + threadIdx.x;   // 131072 = 8192n * 16k
    int n = idx >> 4, k = idx & 15;
    float x0 = r[n * 4 + 0], x1 = r[n * 4 + 1];
    float q0 = x0 * Wa1[2 * k]     + x1 * Wa1[32 + 2 * k];
    float q1 = x0 * Wa1[2 * k + 1] + x1 * Wa1[32 + 2 * k + 1];
    g_qa2[n * 16 + k] = make_float2(q0, q1);
}

// ---------------------------------------------------------------------------
// Attention: per block, TN consecutive n's; thread p = threadIdx.x (P=512).
// logit(n,p) = relu(relu(qa[n]+ca[p]) @ Wa2) @ Wa3, softmax over p,
// pool with coeff_y, then 4->32->16 MLP -> g_c.
__global__ __launch_bounds__(512) void attn_kernel(
    const float* __restrict__ coeff_y,
    const float* __restrict__ Wa2,
    const float* __restrict__ Wa3,
    const float* __restrict__ Wp1, const float* __restrict__ bp1,
    const float* __restrict__ Wp2, const float* __restrict__ bp2)
{
    __shared__ __align__(16) float sWa2[1024];
    __shared__ float sMax[16];
    __shared__ float sRed[16][5];
    __shared__ float sPool[5];
    __shared__ float sHp[32];

    const int tid  = threadIdx.x;
    const int lane = tid & 31, warp = tid >> 5;

    sWa2[tid]       = Wa2[tid];
    sWa2[tid + 512] = Wa2[tid + 512];
    const float4 cy = reinterpret_cast<const float4*>(coeff_y)[tid];
    const int n0 = blockIdx.x * TN;
    __syncthreads();

    for (int t = 0; t < TN; ++t) {
        const int n = n0 + t;

        ULL acc[16];
#pragma unroll
        for (int q = 0; q < 16; ++q) acc[q] = 0ull;

#pragma unroll
        for (int k = 0; k < 16; ++k) {
            float2 ca = g_ca2T[k * 512 + tid];   // coalesced, L1-hot
            float2 qa = g_qa2[n * 16 + k];       // broadcast
            ULL dlo = dup2(fmaxf(qa.x + ca.x, 0.f));   // h1[2k]
            ULL dhi = dup2(fmaxf(qa.y + ca.y, 0.f));   // h1[2k+1]
            const ulonglong2* r0 = reinterpret_cast<const ulonglong2*>(sWa2 + 64 * k);
#pragma unroll
            for (int q = 0; q < 8; ++q) {
                ulonglong2 w0 = r0[q];       // Wa2 row 2k,   cols [4q..4q+3]
                ulonglong2 w1 = r0[q + 8];   // Wa2 row 2k+1, cols [4q..4q+3]
                acc[2 * q]     = fma2(dlo, w0.x, acc[2 * q]);
                acc[2 * q + 1] = fma2(dlo, w0.y, acc[2 * q + 1]);
                acc[2 * q]     = fma2(dhi, w1.x, acc[2 * q]);
                acc[2 * q + 1] = fma2(dhi, w1.y, acc[2 * q + 1]);
            }
        }

        float logit = 0.f;
#pragma unroll
        for (int q = 0; q < 16; ++q) {
            float2 a = unpk(acc[q]);
            float2 w = reinterpret_cast<const float2*>(Wa3)[q];
            logit += fmaxf(a.x, 0.f) * w.x + fmaxf(a.y, 0.f) * w.y;
        }

        // --- softmax over 512 threads ---
        float m = logit;
#pragma unroll
        for (int off = 16; off; off >>= 1)
            m = fmaxf(m, __shfl_xor_sync(0xffffffffu, m, off));
        if (lane == 0) sMax[warp] = m;
        __syncthreads();
        float gm = sMax[0];
#pragma unroll
        for (int w = 1; w < 16; ++w) gm = fmaxf(gm, sMax[w]);

        float e = expf(logit - gm);
        float v0 = e, v1 = e * cy.x, v2 = e * cy.y, v3 = e * cy.z, v4 = e * cy.w;
#pragma unroll
        for (int off = 16; off; off >>= 1) {
            v0 += __shfl_xor_sync(0xffffffffu, v0, off);
            v1 += __shfl_xor_sync(0xffffffffu, v1, off);
            v2 += __shfl_xor_sync(0xffffffffu, v2, off);
            v3 += __shfl_xor_sync(0xffffffffu, v3, off);
            v4 += __shfl_xor_sync(0xffffffffu, v4, off);
        }
        if (lane == 0) {
            sRed[warp][0] = v0; sRed[warp][1] = v1; sRed[warp][2] = v2;
            sRed[warp][3] = v3; sRed[warp][4] = v4;
        }
        __syncthreads();
        if (tid < 5) {
            float s = 0.f;
#pragma unroll
            for (int w = 0; w < 16; ++w) s += sRed[w][tid];
            sPool[tid] = s;
        }
        __syncthreads();

        // --- pooled projection: c = relu(ao@Wp1+bp1)@Wp2+bp2 ---
        if (tid < 32) {
            float inv = 1.f / sPool[0];
            float a0 = sPool[1] * inv, a1 = sPool[2] * inv;
            float a2 = sPool[3] * inv, a3 = sPool[4] * inv;
            float hp = bp1[tid] + a0 * Wp1[tid] + a1 * Wp1[32 + tid]
                                + a2 * Wp1[64 + tid] + a3 * Wp1[96 + tid];
            sHp[tid] = fmaxf(hp, 0.f);
        }
        __syncthreads();
        if (tid < 16) {
            float cv = bp2[tid];
#pragma unroll
            for (int k2 = 0; k2 < 32; ++k2) cv += sHp[k2] * Wp2[k2 * 16 + tid];
            g_c[n * 16 + tid] = cv;
        }
        __syncthreads();
    }
}

// ---------------------------------------------------------------------------
// Gating: out = exp(relu(relu(x@Wg1+bg1)@Wg2+bg2)@Wg3+bg3), x=[r,r',c] (24)
// Block handles 32 rows. Stage A -> G1 transposed in smem; Stage B streams Wg2.
__global__ __launch_bounds__(256) void gate_kernel(
    const float* __restrict__ r, const float* __restrict__ rp,
    const float* __restrict__ Wg1, const float* __restrict__ bg1,
    const float* __restrict__ Wg2, const float* __restrict__ bg2,
    const float* __restrict__ Wg3, const float* __restrict__ bg3,
    float* __restrict__ out)
{
    __shared__ float sX[32][25];        // padded rows
    __shared__ float sG1[256 * 32];     // [k][row]
    __shared__ float sPart[256];

    const int tid = threadIdx.x;
    const int n0 = blockIdx.x * 32;
    const int rr = tid & 31, grp = tid >> 5;   // grp in [0,8)

    for (int idx = tid; idx < 32 * 24; idx += 256) {
        int row = idx / 24, j = idx % 24;
        int n = n0 + row;
        float v = (j < 4) ? r[n * 4 + j]
                : (j < 8) ? rp[n * 4 + (j - 4)]
                          : g_c[n * 16 + (j - 8)];
        sX[row][j] = v;
    }
    __syncthreads();

    // Stage A: G1 = relu(X @ Wg1 + bg1)
    float x[24];
#pragma unroll
    for (int j = 0; j < 24; ++j) x[j] = sX[rr][j];
    const int kbase = grp * 32;
    for (int kk = 0; kk < 32; ++kk) {
        int k = kbase + kk;
        float a = bg1[k];
#pragma unroll
        for (int j = 0; j < 24; ++j) a += x[j] * Wg1[j * 256 + k];  // broadcast LDG
        sG1[k * 32 + rr] = fmaxf(a, 0.f);
    }
    __syncthreads();

    // Stage B: partial over 32 j-columns: sum_j relu(G1@Wg2+bg2)[j]*Wg3[j]
    const int jb = grp * 32;
    ULL acc2[16];
    const ULL* bg2v = reinterpret_cast<const ULL*>(bg2 + jb);
#pragma unroll
    for (int q = 0; q < 16; ++q) acc2[q] = bg2v[q];

#pragma unroll 4
    for (int k = 0; k < 256; ++k) {
        float g1 = sG1[k * 32 + rr];
        ULL gd = dup2(g1);
        const ulonglong2* w = reinterpret_cast<const ulonglong2*>(Wg2 + k * 256 + jb);
#pragma unroll
        for (int q = 0; q < 8; ++q) {
            ulonglong2 wv = w[q];    // broadcast LDG.128 (L2-resident)
            acc2[2 * q]     = fma2(gd, wv.x, acc2[2 * q]);
            acc2[2 * q + 1] = fma2(gd, wv.y, acc2[2 * q + 1]);
        }
    }

    float part = 0.f;
    const float2* w3 = reinterpret_cast<const float2*>(Wg3 + jb);
#pragma unroll
    for (int q = 0; q < 16; ++q) {
        float2 a = unpk(acc2[q]);
        float2 wv = w3[q];
        part += fmaxf(a.x, 0.f) * wv.x + fmaxf(a.y, 0.f) * wv.y;
    }
    sPart[tid] = part;
    __syncthreads();

    if (tid < 32) {
        float s = bg3[0];
#pragma unroll
        for (int g = 0; g < 8; ++g) s += sPart[g * 32 + tid];
        out[n0 + tid] = expf(s);
    }
}

// ---------------------------------------------------------------------------
extern "C" void kernel_launch(void* const* d_in, const int* in_sizes, int n_in,
                              void* d_out, int out_size) {
    (void)in_sizes; (void)n_in; (void)out_size;
    const float* r   = (const float*)d_in[0];
    const float* rp  = (const float*)d_in[1];
    const float* cx  = (const float*)d_in[2];
    const float* cy  = (const float*)d_in[3];
    const float* Wa1 = (const float*)d_in[4];
    const float* Wa2 = (const float*)d_in[5];
    const float* Wa3 = (const float*)d_in[6];
    const float* Wp1 = (const float*)d_in[7];
    const float* bp1 = (const float*)d_in[8];
    const float* Wp2 = (const float*)d_in[9];
    const float* bp2 = (const float*)d_in[10];
    const float* Wg1 = (const float*)d_in[11];
    const float* bg1 = (const float*)d_in[12];
    const float* Wg2 = (const float*)d_in[13];
    const float* bg2 = (const float*)d_in[14];
    const float* Wg3 = (const float*)d_in[15];
    const float* bg3 = (const float*)d_in[16];
    float* out = (float*)d_out;

    pre_ca<<<16, 512>>>(cx, Wa1);
    pre_qa<<<512, 256>>>(r, Wa1);
    attn_kernel<<<N_TOT / TN, 512>>>(cy, Wa2, Wa3, Wp1, bp1, Wp2, bp2);
    gate_kernel<<<N_TOT / 32, 256>>>(r, rp, Wg1, bg1, Wg2, bg2, Wg3, bg3, out);
}